// round 15
// baseline (speedup 1.0000x reference)
#include <cuda_runtime.h>
#include <cuda_fp16.h>
#include <cstdint>

#define BB 2
#define NNx 768
#define DDx 512
#define HHx 16
#define DHx 32
#define INNERx 512
#define PDx 128
#define NEG_INFx -10000.0f
#define LN_EPS 1e-5f

typedef unsigned long long u64;

// ---------------- helpers ----------------
__device__ __forceinline__ void ffma2(u64& d, u64 a, u64 b) {
    asm("fma.rn.f32x2 %0, %1, %2, %0;" : "+l"(d) : "l"(a), "l"(b));
}
__device__ __forceinline__ float2 up2(u64 v) {
    float2 f;
    asm("mov.b64 {%0, %1}, %2;" : "=f"(f.x), "=f"(f.y) : "l"(v));
    return f;
}
__device__ __forceinline__ u64 splat2(float x) {
    u64 r;
    asm("mov.b64 %0, {%1, %1};" : "=l"(r) : "f"(x));
    return r;
}
__device__ __forceinline__ uint32_t f2tf32(float f) {
    uint32_t r;
    asm("cvt.rna.tf32.f32 %0, %1;" : "=r"(r) : "f"(f));
    return r;
}
__device__ __forceinline__ void mma_tf32(float& c0, float& c1, float& c2, float& c3,
                                         uint32_t a0, uint32_t a1, uint32_t a2, uint32_t a3,
                                         uint32_t b0, uint32_t b1) {
    asm("mma.sync.aligned.m16n8k8.row.col.f32.tf32.tf32.f32 "
        "{%0,%1,%2,%3}, {%4,%5,%6,%7}, {%8,%9}, {%0,%1,%2,%3};"
        : "+f"(c0), "+f"(c1), "+f"(c2), "+f"(c3)
        : "r"(a0), "r"(a1), "r"(a2), "r"(a3), "r"(b0), "r"(b1));
}

// ---------------- scratch ----------------
__device__ float g_x[BB * NNx * DDx];
__device__ float g_qkvg[BB * NNx * 2048];
__device__ float g_qh[BB * HHx * NNx * DHx];
__device__ float g_khT[BB * HHx * DHx * NNx];
__device__ float g_vh[BB * HHx * NNx * DHx];
__device__ __half g_bias[(size_t)BB * HHx * NNx * NNx];
__device__ float g_og[BB * NNx * INNERx];

// ---------------- K0: node LayerNorm (standalone; runs on main stream) ----------------
__global__ __launch_bounds__(128) void k_ln_node(const float* __restrict__ node,
                                                 const float* __restrict__ nnw,
                                                 const float* __restrict__ nnb) {
    int row = blockIdx.x, tid = threadIdx.x;
    const float* in = node + (size_t)row * DDx;
    float s = 0.f, ss = 0.f;
    for (int c = tid; c < DDx; c += 128) {
        float t = in[c];
        s += t; ss += t * t;
    }
#pragma unroll
    for (int o = 16; o > 0; o >>= 1) {
        s  += __shfl_xor_sync(~0u, s, o);
        ss += __shfl_xor_sync(~0u, ss, o);
    }
    __shared__ float red[8];
    int wd = tid >> 5, ln = tid & 31;
    if (ln == 0) { red[wd] = s; red[4 + wd] = ss; }
    __syncthreads();
    __shared__ float sm2, sr2;
    if (tid == 0) {
        float S = red[0] + red[1] + red[2] + red[3];
        float SS = red[4] + red[5] + red[6] + red[7];
        float m = S / DDx;
        sm2 = m;
        sr2 = rsqrtf(SS / DDx - m * m + LN_EPS);
    }
    __syncthreads();
    float m = sm2, r = sr2;
    for (int c = tid; c < DDx; c += 128)
        g_x[(size_t)row * DDx + c] = (in[c] - m) * r * nnw[c] + nnb[c];
}

// ---------------- K1: pair bias — persistent, cp.async, inline prep (side stream) ----------------
#define SPS 132
#define PB_TR 64
#define PB_GRID 444
#define PB_TILES (BB * NNx * 12)
#define PB_TILE_F (PB_TR * SPS)
#define PB_SMEM  (2 * PB_TILE_F * 4)             // 67584 B
__device__ __forceinline__ size_t pb_decode(int T, int& b, int& i, int& jt) {
    b = T / (NNx * 12);
    int rem = T - b * (NNx * 12);
    i = rem / 12;
    jt = rem - i * 12;
    return ((size_t)(b * NNx + i)) * NNx + jt * PB_TR;
}
__device__ __forceinline__ void pb_stage(float* buf, const float* pb, int tid) {
#pragma unroll
    for (int it = 0; it < 16; it++) {
        int f = tid + it * 128;
        int r = f >> 5, c4 = (f & 31) << 2;
        unsigned sa = (unsigned)__cvta_generic_to_shared(buf + r * SPS + c4);
        const float* ga = pb + (size_t)r * PDx + c4;
        asm volatile("cp.async.cg.shared.global [%0], [%1], 16;" :: "r"(sa), "l"(ga));
    }
    asm volatile("cp.async.commit_group;");
}
__global__ __launch_bounds__(128, 3) void k_pairbias(
    const float* __restrict__ pair, const int* __restrict__ mask,
    const float* __restrict__ bias_w, const float* __restrict__ pnw, const float* __restrict__ pnb) {
    extern __shared__ __align__(16) float sp[];
    int tid = threadIdx.x;
    int w = tid >> 5, lane = tid & 31;
    int lg = lane >> 2, lt = lane & 3;
    int r0 = w * 16 + lg;

    uint32_t blo[32], bhi[32];
#pragma unroll
    for (int ks = 0; ks < 16; ks++) {
        int e0 = ks * 8 + lt, e1 = ks * 8 + lt + 4;
        blo[2 * ks]     = f2tf32(pnw[e0] * bias_w[e0 * HHx + lg]);
        blo[2 * ks + 1] = f2tf32(pnw[e1] * bias_w[e1 * HHx + lg]);
        bhi[2 * ks]     = f2tf32(pnw[e0] * bias_w[e0 * HHx + 8 + lg]);
        bhi[2 * ks + 1] = f2tf32(pnw[e1] * bias_w[e1 * HHx + 8 + lg]);
    }
    float shv[4], thv[4];
    {
        int hc[4] = {2 * lt, 2 * lt + 1, 8 + 2 * lt, 9 + 2 * lt};
#pragma unroll
        for (int q = 0; q < 4; q++) {
            float s = 0.f, t = 0.f;
            for (int e = 0; e < PDx; e++) {
                float bw = bias_w[e * HHx + hc[q]];
                s += pnw[e] * bw;
                t += pnb[e] * bw;
            }
            shv[q] = s; thv[q] = t;
        }
    }

    const int g = PB_GRID;
    {
        int b, i, jt;
        size_t rb = pb_decode(blockIdx.x, b, i, jt);
        pb_stage(sp, pair + rb * (size_t)PDx, tid);
    }

    int parity = 0;
    for (int T = blockIdx.x; T < PB_TILES; T += g) {
        asm volatile("cp.async.wait_group 0;" ::: "memory");
        __syncthreads();

        int Tn = T + g;
        if (Tn < PB_TILES) {
            int b2, i2, jt2;
            size_t rb2 = pb_decode(Tn, b2, i2, jt2);
            pb_stage(sp + (parity ^ 1) * PB_TILE_F, pair + rb2 * (size_t)PDx, tid);
        }

        int b, i, jt;
        size_t rowbase = pb_decode(T, b, i, jt);
        const float* buf = sp + parity * PB_TILE_F;

        float e0 = 0.f, e1 = 0.f, e2 = 0.f, e3 = 0.f;
        float o0 = 0.f, o1 = 0.f, o2 = 0.f, o3 = 0.f;
        float E0 = 0.f, E1 = 0.f, E2 = 0.f, E3 = 0.f;
        float O0 = 0.f, O1 = 0.f, O2 = 0.f, O3 = 0.f;
        float s0 = 0.f, ss0 = 0.f, s1 = 0.f, ss1 = 0.f;
        const float* Ab = buf + r0 * SPS + lt;
#pragma unroll
        for (int kp = 0; kp < 8; kp++) {
            {
                int ks = 2 * kp;
                float a0 = Ab[ks * 8];
                float a1 = Ab[ks * 8 + 8 * SPS];
                float a2 = Ab[ks * 8 + 4];
                float a3 = Ab[ks * 8 + 8 * SPS + 4];
                s0 += a0 + a2;  ss0 += a0 * a0 + a2 * a2;
                s1 += a1 + a3;  ss1 += a1 * a1 + a3 * a3;
                uint32_t u0 = __float_as_uint(a0), u1 = __float_as_uint(a1);
                uint32_t u2 = __float_as_uint(a2), u3 = __float_as_uint(a3);
                mma_tf32(e0, e1, e2, e3, u0, u1, u2, u3, blo[2 * ks], blo[2 * ks + 1]);
                mma_tf32(E0, E1, E2, E3, u0, u1, u2, u3, bhi[2 * ks], bhi[2 * ks + 1]);
            }
            {
                int ks = 2 * kp + 1;
                float a0 = Ab[ks * 8];
                float a1 = Ab[ks * 8 + 8 * SPS];
                float a2 = Ab[ks * 8 + 4];
                float a3 = Ab[ks * 8 + 8 * SPS + 4];
                s0 += a0 + a2;  ss0 += a0 * a0 + a2 * a2;
                s1 += a1 + a3;  ss1 += a1 * a1 + a3 * a3;
                uint32_t u0 = __float_as_uint(a0), u1 = __float_as_uint(a1);
                uint32_t u2 = __float_as_uint(a2), u3 = __float_as_uint(a3);
                mma_tf32(o0, o1, o2, o3, u0, u1, u2, u3, blo[2 * ks], blo[2 * ks + 1]);
                mma_tf32(O0, O1, O2, O3, u0, u1, u2, u3, bhi[2 * ks], bhi[2 * ks + 1]);
            }
        }
        float c0 = e0 + o0, c1 = e1 + o1, c2 = e2 + o2, c3 = e3 + o3;
        float c4v = E0 + O0, c5 = E1 + O1, c6 = E2 + O2, c7 = E3 + O3;

        s0  += __shfl_xor_sync(~0u, s0, 1);   s0  += __shfl_xor_sync(~0u, s0, 2);
        ss0 += __shfl_xor_sync(~0u, ss0, 1);  ss0 += __shfl_xor_sync(~0u, ss0, 2);
        s1  += __shfl_xor_sync(~0u, s1, 1);   s1  += __shfl_xor_sync(~0u, s1, 2);
        ss1 += __shfl_xor_sync(~0u, ss1, 1);  ss1 += __shfl_xor_sync(~0u, ss1, 2);
        float m0 = s0 * (1.0f / PDx);
        float r0s = rsqrtf(ss0 * (1.0f / PDx) - m0 * m0 + LN_EPS);
        float m1 = s1 * (1.0f / PDx);
        float r1s = rsqrtf(ss1 * (1.0f / PDx) - m1 * m1 + LN_EPS);

        int mk0 = mask[rowbase + r0];
        int mk1 = mask[rowbase + r0 + 8];

        size_t pb0 = (((size_t)(b * HHx) * NNx + i)) * NNx + jt * PB_TR;
        float rm0 = r0s * m0, rm1 = r1s * m1;
        float vals[8] = {
            r0s * c0  - rm0 * shv[0] + thv[0],
            r0s * c1  - rm0 * shv[1] + thv[1],
            r1s * c2  - rm1 * shv[0] + thv[0],
            r1s * c3  - rm1 * shv[1] + thv[1],
            r0s * c4v - rm0 * shv[2] + thv[2],
            r0s * c5  - rm0 * shv[3] + thv[3],
            r1s * c6  - rm1 * shv[2] + thv[2],
            r1s * c7  - rm1 * shv[3] + thv[3],
        };
        if (mk0 == 0) { vals[0] = NEG_INFx; vals[1] = NEG_INFx; vals[4] = NEG_INFx; vals[5] = NEG_INFx; }
        if (mk1 == 0) { vals[2] = NEG_INFx; vals[3] = NEG_INFx; vals[6] = NEG_INFx; vals[7] = NEG_INFx; }
        int hcol[4] = {2 * lt, 2 * lt + 1, 8 + 2 * lt, 9 + 2 * lt};
        size_t plane = (size_t)NNx * NNx;
        g_bias[pb0 + hcol[0] * plane + r0]     = __float2half_rn(vals[0]);
        g_bias[pb0 + hcol[1] * plane + r0]     = __float2half_rn(vals[1]);
        g_bias[pb0 + hcol[0] * plane + r0 + 8] = __float2half_rn(vals[2]);
        g_bias[pb0 + hcol[1] * plane + r0 + 8] = __float2half_rn(vals[3]);
        g_bias[pb0 + hcol[2] * plane + r0]     = __float2half_rn(vals[4]);
        g_bias[pb0 + hcol[3] * plane + r0]     = __float2half_rn(vals[5]);
        g_bias[pb0 + hcol[2] * plane + r0 + 8] = __float2half_rn(vals[6]);
        g_bias[pb0 + hcol[3] * plane + r0 + 8] = __float2half_rn(vals[7]);

        parity ^= 1;
    }
}

// ---------------- K2/K5: dense GEMM (tf32 mma, double-buffered) ----------------
#define AST 20
#define BST 72
template<int MODE>
__global__ void k_gemm_tc(const float* __restrict__ B1, const float* __restrict__ B2,
                          const float* __restrict__ bias1, const float* __restrict__ bias2,
                          float* __restrict__ Cext) {
    constexpr int LDC   = (MODE == 0) ? 2048 : 512;
    constexpr int SPLIT = (MODE == 0) ? 1536 : (1 << 30);
    constexpr int LD1   = (MODE == 0) ? 1536 : 512;
    constexpr int LD2   = 512;

    const float* A = (MODE == 0) ? g_x : g_og;
    float* C = (MODE == 0) ? g_qkvg : Cext;

    __shared__ __align__(16) float As[2][128 * AST];
    __shared__ __align__(16) float Bs[2][16 * BST];

    int bm = blockIdx.y * 128, bn = blockIdx.x * 64;
    int tid = threadIdx.x, w = tid >> 5, lane = tid & 31;
    int wm = w >> 1, wn = w & 1;
    int lg = lane >> 2, lt = lane & 3;

    float acc[2][4][4] = {};

    int mS = tid >> 1, segS = (tid & 1) * 8;
    int kS = tid >> 4, nS = (tid & 15) * 4;
    int ncol = bn + nS;
    const float* bsrc = (ncol < SPLIT) ? (B1 + ncol) : (B2 + (ncol - SPLIT));
    int ldb = (ncol < SPLIT) ? LD1 : LD2;
    const float* aS = A + (size_t)(bm + mS) * 512 + segS;

    float4 ra0, ra1, rb;
    ra0 = *(const float4*)(aS);
    ra1 = *(const float4*)(aS + 4);
    rb  = *(const float4*)&bsrc[(size_t)kS * ldb];
    {
        uint4 t0 = {f2tf32(ra0.x), f2tf32(ra0.y), f2tf32(ra0.z), f2tf32(ra0.w)};
        uint4 t1 = {f2tf32(ra1.x), f2tf32(ra1.y), f2tf32(ra1.z), f2tf32(ra1.w)};
        uint4 tb = {f2tf32(rb.x),  f2tf32(rb.y),  f2tf32(rb.z),  f2tf32(rb.w)};
        *(uint4*)&As[0][mS * AST + segS]     = t0;
        *(uint4*)&As[0][mS * AST + segS + 4] = t1;
        *(uint4*)&Bs[0][kS * BST + nS]       = tb;
    }
    __syncthreads();

    for (int k0 = 0; k0 < 512; k0 += 16) {
        int cur = (k0 >> 4) & 1;
        bool more = (k0 + 16) < 512;
        if (more) {
            ra0 = *(const float4*)(aS + k0 + 16);
            ra1 = *(const float4*)(aS + k0 + 20);
            rb  = *(const float4*)&bsrc[(size_t)(k0 + 16 + kS) * ldb];
        }

#pragma unroll
        for (int ks = 0; ks < 2; ks++) {
            uint32_t af[2][4];
            const float* ab = &As[cur][(wm * 32 + lg) * AST + ks * 8 + lt];
#pragma unroll
            for (int mf = 0; mf < 2; mf++) {
                const float* a = ab + mf * 16 * AST;
                af[mf][0] = __float_as_uint(a[0]);
                af[mf][1] = __float_as_uint(a[8 * AST]);
                af[mf][2] = __float_as_uint(a[4]);
                af[mf][3] = __float_as_uint(a[8 * AST + 4]);
            }
            uint32_t bf[4][2];
            const float* bb = &Bs[cur][(ks * 8 + lt) * BST + wn * 32 + lg];
#pragma unroll
            for (int nf = 0; nf < 4; nf++) {
                bf[nf][0] = __float_as_uint(bb[nf * 8]);
                bf[nf][1] = __float_as_uint(bb[4 * BST + nf * 8]);
            }
#pragma unroll
            for (int mf = 0; mf < 2; mf++)
#pragma unroll
                for (int nf = 0; nf < 4; nf++)
                    mma_tf32(acc[mf][nf][0], acc[mf][nf][1], acc[mf][nf][2], acc[mf][nf][3],
                             af[mf][0], af[mf][1], af[mf][2], af[mf][3],
                             bf[nf][0], bf[nf][1]);
        }

        if (more) {
            int nxt = cur ^ 1;
            uint4 t0 = {f2tf32(ra0.x), f2tf32(ra0.y), f2tf32(ra0.z), f2tf32(ra0.w)};
            uint4 t1 = {f2tf32(ra1.x), f2tf32(ra1.y), f2tf32(ra1.z), f2tf32(ra1.w)};
            uint4 tb = {f2tf32(rb.x),  f2tf32(rb.y),  f2tf32(rb.z),  f2tf32(rb.w)};
            *(uint4*)&As[nxt][mS * AST + segS]     = t0;
            *(uint4*)&As[nxt][mS * AST + segS + 4] = t1;
            *(uint4*)&Bs[nxt][kS * BST + nS]       = tb;
        }
        __syncthreads();
    }

#pragma unroll
    for (int mf = 0; mf < 2; mf++) {
#pragma unroll
        for (int nf = 0; nf < 4; nf++) {
            int r = bm + wm * 32 + mf * 16 + lg;
            int c = bn + wn * 32 + nf * 8 + 2 * lt;
            float bi0 = (c < SPLIT) ? bias1[c] : bias2[c - SPLIT];
            float bi1 = (c + 1 < SPLIT) ? bias1[c + 1] : bias2[c + 1 - SPLIT];
            float2 v0 = {acc[mf][nf][0] + bi0, acc[mf][nf][1] + bi1};
            float2 v1 = {acc[mf][nf][2] + bi0, acc[mf][nf][3] + bi1};
            *(float2*)&C[(size_t)r * LDC + c]       = v0;
            *(float2*)&C[(size_t)(r + 8) * LDC + c] = v1;
        }
    }
}

// ---------------- K3: q/k LN; q,v head-major, k transposed ----------------
__global__ void k_lnqk(const float* __restrict__ qw, const float* __restrict__ qb,
                       const float* __restrict__ kw, const float* __restrict__ kb) {
    int bn = blockIdx.x;
    const float* row = g_qkvg + (size_t)bn * 2048;
    int b = bn / NNx, nn = bn % NNx;
    float s1 = 0.f, ss1 = 0.f, s2 = 0.f, ss2 = 0.f;
    for (int c = threadIdx.x; c < 512; c += 256) {
        float a = row[c], b2 = row[512 + c];
        s1 += a; ss1 += a * a; s2 += b2; ss2 += b2 * b2;
    }
#pragma unroll
    for (int o = 16; o > 0; o >>= 1) {
        s1  += __shfl_xor_sync(~0u, s1, o);  ss1 += __shfl_xor_sync(~0u, ss1, o);
        s2  += __shfl_xor_sync(~0u, s2, o);  ss2 += __shfl_xor_sync(~0u, ss2, o);
    }
    __shared__ float red[4][8];
    int w = threadIdx.x >> 5, lane = threadIdx.x & 31;
    if (lane == 0) { red[0][w] = s1; red[1][w] = ss1; red[2][w] = s2; red[3][w] = ss2; }
    __syncthreads();
    __shared__ float st[4];
    if (threadIdx.x == 0) {
        float a = 0.f, bb = 0.f, c = 0.f, d = 0.f;
        for (int i = 0; i < 8; i++) { a += red[0][i]; bb += red[1][i]; c += red[2][i]; d += red[3][i]; }
        float m1 = a / 512.f, m2 = c / 512.f;
        st[0] = m1; st[1] = rsqrtf(bb / 512.f - m1 * m1 + LN_EPS);
        st[2] = m2; st[3] = rsqrtf(d / 512.f - m2 * m2 + LN_EPS);
    }
    __syncthreads();
    float m1 = st[0], r1 = st[1], m2 = st[2], r2 = st[3];
    for (int c = threadIdx.x; c < 512; c += 256) {
        int h = c >> 5, d = c & 31;
        size_t oidx  = (((size_t)(b * HHx + h)) * NNx + nn) * DHx + d;
        size_t oidxT = (((size_t)(b * HHx + h)) * DHx + d) * NNx + nn;
        g_qh[oidx]   = (row[c]       - m1) * r1 * qw[c] + qb[c];
        g_khT[oidxT] = (row[512 + c] - m2) * r2 * kw[c] + kb[c];
        g_vh[oidx]   = row[1024 + c];
    }
}

// ---------------- K4: attention — 16 rows, 12 warps; QK with pre-splatted q ----------------
#define AR 16
#define AT_S_OFF    0
#define AT_SQ_OFF   (AR * NNx * 4)                     // 49152
#define AT_PART_OFF (AT_SQ_OFF + AR * 32 * 8)          // +4096
#define AT_INV_OFF  (AT_PART_OFF + 12 * AR * 32 * 4)   // +24576
#define AT_SMEM     (AT_INV_OFF + AR * 4)              // 77888 B
__global__ __launch_bounds__(384, 2) void k_attn() {
    extern __shared__ __align__(16) char smraw[];
    float (*S)[NNx]       = (float(*)[NNx])(smraw + AT_S_OFF);
    u64   (*sQ)[DHx]      = (u64(*)[DHx])(smraw + AT_SQ_OFF);      // pre-splatted q
    float (*part)[AR][32] = (float(*)[AR][32])(smraw + AT_PART_OFF);
    float* invs           = (float*)(smraw + AT_INV_OFF);

    int i0 = blockIdx.x * AR;
    int h = blockIdx.y, b = blockIdx.z;
    int tid = threadIdx.x;
    int w = tid >> 5, lane = tid & 31;
    size_t bhbase = (size_t)(b * HHx + h) * NNx;

    for (int idx = tid; idx < AR * DHx; idx += 384) {
        int r = idx >> 5, d = idx & 31;
        float qv = g_qh[(bhbase + i0 + r) * DHx + d];
        sQ[r][d] = splat2(qv);
    }
    __syncthreads();

    const float scale = 0.17677669529663687f;
    const float* kT = g_khT + (size_t)(b * HHx + h) * DHx * NNx;

    // ---- QK^T: warp -> (j-chunk 128, row-half 8); lane owns 4 j ----
    {
        int jc = w >> 1, rh = w & 1;
        int jb = jc * 128 + lane * 4;
        int rbase = rh * 8;
        const float* kTc = kT + jb;
        u64 acc[8][2];
#pragma unroll
        for (int r = 0; r < 8; r++) { acc[r][0] = 0; acc[r][1] = 0; }

#pragma unroll
        for (int dg = 0; dg < 8; dg++) {
            u64 kx[4][2];
#pragma unroll
            for (int dd = 0; dd < 4; dd++) {
                ulonglong2 kv = *(const ulonglong2*)&kTc[(size_t)(dg * 4 + dd) * NNx];
                kx[dd][0] = kv.x; kx[dd][1] = kv.y;
            }
#pragma unroll
            for (int r = 0; r < 8; r++) {
                const u64* qrow = &sQ[rbase + r][dg * 4];
#pragma unroll
                for (int dd = 0; dd < 4; dd++) {
                    u64 qs = qrow[dd];             // broadcast LDS.64
                    ffma2(acc[r][0], kx[dd][0], qs);
                    ffma2(acc[r][1], kx[dd][1], qs);
                }
            }
        }

#pragma unroll
        for (int r = 0; r < 8; r++) {
            int row = rbase + r;
            const __half* brow = g_bias + (bhbase + i0 + row) * NNx + jb;
            __half2 b01 = *(const __half2*)(brow);
            __half2 b23 = *(const __half2*)(brow + 2);
            float2 f01 = __half22float2(b01), f23 = __half22float2(b23);
            float2 sx = up2(acc[r][0]), sy = up2(acc[r][1]);
            float4 out = {sx.x * scale + f01.x, sx.y * scale + f01.y,
                          sy.x * scale + f23.x, sy.y * scale + f23.y};
            *(float4*)&S[row][jb] = out;
        }
    }
    __syncthreads();

    // ---- softmax: rows r = w, w+12 ----
    for (int r = w; r < AR; r += 12) {
        float* Sr = &S[r][0];
        float mx = -3.4e38f;
        for (int c = lane; c < NNx; c += 32) mx = fmaxf(mx, Sr[c]);
#pragma unroll
        for (int o = 16; o > 0; o >>= 1) mx = fmaxf(mx, __shfl_xor_sync(~0u, mx, o));
        float sum = 0.f;
        for (int c = lane; c < NNx; c += 32) {
            float e = __expf(Sr[c] - mx);
            Sr[c] = e;
            sum += e;
        }
#pragma unroll
        for (int o = 16; o > 0; o >>= 1) sum += __shfl_xor_sync(~0u, sum, o);
        if (lane == 0) invs[r] = 1.0f / sum;
    }
    __syncthreads();

    // ---- AV: warp w owns 64-j chunk; half-warps split it; partials for 16 rows ----
    {
        int dp = lane & 15, jh = lane >> 4;
        int jb = w * 64 + jh * 32;
        const float* vbase = g_vh + bhbase * DHx + 2 * dp;
        float acc[AR][2];
#pragma unroll
        for (int r = 0; r < AR; r++) { acc[r][0] = 0.f; acc[r][1] = 0.f; }

#pragma unroll 2
        for (int jj = 0; jj < 32; jj += 4) {
            int j = jb + jj;
            const float* vp = vbase + (size_t)j * DHx;
            float2 v0 = *(const float2*)(vp);
            float2 v1 = *(const float2*)(vp + 32);
            float2 v2 = *(const float2*)(vp + 64);
            float2 v3 = *(const float2*)(vp + 96);
#pragma unroll
            for (int r = 0; r < AR; r++) {
                float4 p = *(const float4*)&S[r][j];
                acc[r][0] += p.x * v0.x + p.y * v1.x + p.z * v2.x + p.w * v3.x;
                acc[r][1] += p.x * v0.y + p.y * v1.y + p.z * v2.y + p.w * v3.y;
            }
        }
#pragma unroll
        for (int r = 0; r < AR; r++) {
            acc[r][0] += __shfl_down_sync(~0u, acc[r][0], 16);
            acc[r][1] += __shfl_down_sync(~0u, acc[r][1], 16);
        }
        if (jh == 0) {
#pragma unroll
            for (int r = 0; r < AR; r++) {
                part[w][r][2 * dp]     = acc[r][0];
                part[w][r][2 * dp + 1] = acc[r][1];
            }
        }
    }
    __syncthreads();

    // ---- reduce 12 partials + normalize + sigmoid gate + store ----
    for (int o = tid; o < AR * 32; o += 384) {
        int r = o >> 5, d = o & 31;
        float s = 0.f;
#pragma unroll
        for (int ww = 0; ww < 12; ww++) s += part[ww][r][d];
        s *= invs[r];
        size_t bn = (size_t)b * NNx + i0 + r;
        float gg = g_qkvg[bn * 2048 + 1536 + h * DHx + d];
        float sg = 1.0f / (1.0f + __expf(-gg));
        g_og[bn * INNERx + h * DHx + d] = s * sg;
    }
}

// ---------------- launch: fork pairbias onto a side stream ----------------
extern "C" void kernel_launch(void* const* d_in, const int* in_sizes, int n_in,
                              void* d_out, int out_size) {
    const float* node = (const float*)d_in[0];
    const float* pair = (const float*)d_in[1];
    const int*   mask = (const int*)d_in[2];
    const float* nnw  = (const float*)d_in[3];
    const float* nnb  = (const float*)d_in[4];
    const float* qkvw = (const float*)d_in[5];
    const float* qkvb = (const float*)d_in[6];
    const float* gw   = (const float*)d_in[7];
    const float* gb   = (const float*)d_in[8];
    const float* qlw  = (const float*)d_in[9];
    const float* qlb  = (const float*)d_in[10];
    const float* klw  = (const float*)d_in[11];
    const float* klb  = (const float*)d_in[12];
    const float* pnw  = (const float*)d_in[13];
    const float* pnb  = (const float*)d_in[14];
    const float* bw   = (const float*)d_in[15];
    const float* ow   = (const float*)d_in[16];
    const float* ob   = (const float*)d_in[17];
    float* out = (float*)d_out;

    cudaFuncSetAttribute(k_pairbias, cudaFuncAttributeMaxDynamicSharedMemorySize, PB_SMEM);
    cudaFuncSetAttribute(k_attn, cudaFuncAttributeMaxDynamicSharedMemorySize, AT_SMEM);

    // Fork: pairbias is independent of the LN->GEMM->LNQK chain.
    cudaStream_t sB;
    cudaStreamCreateWithFlags(&sB, cudaStreamNonBlocking);
    cudaEvent_t e1, e2;
    cudaEventCreateWithFlags(&e1, cudaEventDisableTiming);
    cudaEventCreateWithFlags(&e2, cudaEventDisableTiming);

    cudaEventRecord(e1, cudaStreamPerThread);
    cudaStreamWaitEvent(sB, e1, 0);
    k_pairbias<<<PB_GRID, 128, PB_SMEM, sB>>>(pair, mask, bw, pnw, pnb);

    k_ln_node<<<BB * NNx, 128, 0, cudaStreamPerThread>>>(node, nnw, nnb);
    k_gemm_tc<0><<<dim3(2048 / 64, (BB * NNx) / 128), 256, 0, cudaStreamPerThread>>>(qkvw, gw, qkvb, gb, nullptr);
    k_lnqk<<<BB * NNx, 256, 0, cudaStreamPerThread>>>(qlw, qlb, klw, klb);

    cudaEventRecord(e2, sB);
    cudaStreamWaitEvent(cudaStreamPerThread, e2, 0);

    k_attn<<<dim3(NNx / AR, HHx, BB), 384, AT_SMEM, cudaStreamPerThread>>>();
    k_gemm_tc<1><<<dim3(512 / 64, (BB * NNx) / 128), 256, 0, cudaStreamPerThread>>>(ow, ow, ob, ob, out);
    // Intentionally not destroying sB/e1/e2 here: destroying capture-participating
    // objects mid-capture can invalidate the graph. Leak is bounded (few calls).
}